// round 2
// baseline (speedup 1.0000x reference)
#include <cuda_runtime.h>
#include <math_constants.h>

static constexpr int   N_ATOMS = 256;
static constexpr float RCUT    = 6.0f;
static constexpr int   NFEAT   = 24;

__global__ __launch_bounds__(256, 4)
void acsf_kernel(const float* __restrict__ zn,
                 const float* __restrict__ coords,
                 float* __restrict__ out)
{
    const int i    = blockIdx.x;
    const int b    = blockIdx.y;
    const int tid  = threadIdx.x;
    const int lane = tid & 31;
    const int wid  = tid >> 5;

    __shared__ float sdx[N_ATOMS], sdy[N_ATOMS], sdz[N_ATOMS];
    __shared__ float srr[N_ATOMS], ssq[N_ATOMS], sfc[N_ATOMS];
    __shared__ float radw[7][8];
    __shared__ float angw[16][8];
    __shared__ int   wcnt[8], woff[8];
    __shared__ int   sM;

    const float* cb = coords + (size_t)b * N_ATOMS * 3;
    const float xi = cb[3*i+0], yi = cb[3*i+1], zi = cb[3*i+2];

    // ---- Phase 1: pair (i, j=tid) radial terms ----
    const int   j  = tid;
    const float dx = xi - cb[3*j+0];
    const float dy = yi - cb[3*j+1];
    const float dz = zi - cb[3*j+2];
    const float sq = dx*dx + dy*dy + dz*dz;
    const float r  = sqrtf(sq);
    const bool  valid = (j != i) && (r < RCUT);
    const float fc = valid ? 0.5f * (__cosf(CUDART_PI_F * r * (1.0f/RCUT)) + 1.0f)
                           : 0.0f;

    float g[7];
    {
        const float rm2 = r - 2.0f;
        g[0] = fc;
        g[1] = __expf(-0.1f * r  * r  ) * fc;   // (rs=0, eta=0.1)
        g[2] = __expf(-1.0f * r  * r  ) * fc;   // (rs=0, eta=1.0)
        g[3] = __expf(-0.1f * rm2* rm2) * fc;   // (rs=2, eta=0.1)
        g[4] = __expf(-1.0f * rm2* rm2) * fc;   // (rs=2, eta=1.0)
        g[5] = __cosf(1.0f * r) * fc;           // kappa=1
        g[6] = __cosf(2.0f * r) * fc;           // kappa=2
    }
#pragma unroll
    for (int f = 0; f < 7; f++) {
        float v = g[f];
#pragma unroll
        for (int s = 16; s > 0; s >>= 1) v += __shfl_down_sync(0xffffffffu, v, s);
        if (lane == 0) radw[f][wid] = v;
    }

    // ---- Phase 2: deterministic neighbor compaction (ascending j order) ----
    const unsigned bm = __ballot_sync(0xffffffffu, valid);
    const int before = __popc(bm & ((1u << lane) - 1u));
    if (lane == 0) wcnt[wid] = __popc(bm);
    __syncthreads();
    if (tid == 0) {
        int o = 0;
#pragma unroll
        for (int w = 0; w < 8; w++) { woff[w] = o; o += wcnt[w]; }
        sM = o;
    }
    __syncthreads();
    if (valid) {
        const int p = woff[wid] + before;
        sdx[p] = dx; sdy[p] = dy; sdz[p] = dz;
        srr[p] = r;  ssq[p] = sq; sfc[p] = fc;
    }
    __syncthreads();

    const int M      = sM;
    const int npairs = M * (M - 1) / 2;

    // ---- Phase 3: angular sums over neighbor pairs (jj < k), doubled by symmetry ----
    float a3[8] = {0,0,0,0,0,0,0,0};   // G4 (fc3) accumulators
    float a2[8] = {0,0,0,0,0,0,0,0};   // G5 (fc2) accumulators

    for (int idx = tid; idx < npairs; idx += 256) {
        // triangular decode: idx = k*(k-1)/2 + jj, 0 <= jj < k < M
        int k = (int)((sqrtf(8.0f * (float)idx + 1.0f) + 1.0f) * 0.5f);
        while (k * (k - 1) / 2 > idx)       k--;
        while ((k + 1) * k / 2 <= idx)      k++;
        const int jj = idx - k * (k - 1) / 2;

        const float djx = sdx[jj], djy = sdy[jj], djz = sdz[jj];
        const float dkx = sdx[k],  dky = sdy[k],  dkz = sdz[k];
        const float rj  = srr[jj], rk  = srr[k];
        const float sqj = ssq[jj], sqk = ssq[k];
        const float fcj = sfc[jj], fck = sfc[k];

        const float dot = djx*dkx + djy*dky + djz*dkz;
        const float c   = __fdividef(dot, rj * rk);

        const float ex = dkx - djx, ey = dky - djy, ez = dkz - djz;
        const float sqjk = ex*ex + ey*ey + ez*ez;
        const float rjk  = sqrtf(sqjk);
        const float fcjk = (rjk < RCUT)
                         ? 0.5f * (__cosf(CUDART_PI_F * rjk * (1.0f/RCUT)) + 1.0f)
                         : 0.0f;

        const float p  = fmaxf(1.0f + c, 0.0f);
        const float m  = fmaxf(1.0f - c, 0.0f);
        const float p2 = p*p, p4 = p2*p2;
        const float m2 = m*m, m4 = m2*m2;

        const float sq2 = sqj + sqk;
        const float sq3 = sq2 + sqjk;
        const float w2  = fcj * fck;
        const float w3  = w2 * fcjk;

        const float e3a = __expf(-0.01f * sq3) * w3;
        const float e3b = __expf(-0.1f  * sq3) * w3;
        const float e2a = __expf(-0.01f * sq2) * w2;
        const float e2b = __expf(-0.1f  * sq2) * w2;

        a3[0] += m  * e3a;  a3[1] += p  * e3a;
        a3[2] += m4 * e3a;  a3[3] += p4 * e3a;
        a3[4] += m  * e3b;  a3[5] += p  * e3b;
        a3[6] += m4 * e3b;  a3[7] += p4 * e3b;

        a2[0] += m  * e2a;  a2[1] += p  * e2a;
        a2[2] += m4 * e2a;  a2[3] += p4 * e2a;
        a2[4] += m  * e2b;  a2[5] += p  * e2b;
        a2[6] += m4 * e2b;  a2[7] += p4 * e2b;
    }

#pragma unroll
    for (int f = 0; f < 8; f++) {
        float v = a3[f];
        float u = a2[f];
#pragma unroll
        for (int s = 16; s > 0; s >>= 1) {
            v += __shfl_down_sync(0xffffffffu, v, s);
            u += __shfl_down_sync(0xffffffffu, u, s);
        }
        if (lane == 0) { angw[f][wid] = v; angw[8 + f][wid] = u; }
    }
    __syncthreads();

    // ---- Output: thread 0 writes 24 features (fixed summation order) ----
    if (tid == 0) {
        float* o = out + ((size_t)(b * N_ATOMS + i)) * NFEAT;
        o[0] = zn[i];
#pragma unroll
        for (int f = 0; f < 7; f++) {
            float s = 0.0f;
#pragma unroll
            for (int w = 0; w < 8; w++) s += radw[f][w];
            o[1 + f] = s;
        }
        // scale: x2 for j<k symmetry, x 2^(1-zeta) (zeta=1 -> 2.0, zeta=4 -> 0.25)
        const float sc[8] = {2.0f, 2.0f, 0.25f, 0.25f, 2.0f, 2.0f, 0.25f, 0.25f};
#pragma unroll
        for (int f = 0; f < 8; f++) {
            float s3 = 0.0f, s2 = 0.0f;
#pragma unroll
            for (int w = 0; w < 8; w++) { s3 += angw[f][w]; s2 += angw[8 + f][w]; }
            o[8  + f] = s3 * sc[f];
            o[16 + f] = s2 * sc[f];
        }
    }
}

extern "C" void kernel_launch(void* const* d_in, const int* in_sizes, int n_in,
                              void* d_out, int out_size)
{
    const float* zn     = (const float*)d_in[0];   // atomic_numbers [N]
    const float* coords = (const float*)d_in[1];   // coordinates   [B, N, 3]
    float*       out    = (float*)d_out;           // [B, N, 24]

    const int B = in_sizes[1] / (N_ATOMS * 3);
    dim3 grid(N_ATOMS, B);
    acsf_kernel<<<grid, 256>>>(zn, coords, out);
}